// round 1
// baseline (speedup 1.0000x reference)
#include <cuda_runtime.h>
#include <cuda_bf16.h>

#define N_WAVES 128
#define TPB 128
#define PPT 4  // points per thread

// Per-wave precomputed params: (gx = f*cos r, gy = f*sin r, phase0_cycles, amplitude)
__device__ float4 g_wp[N_WAVES];

__global__ void prep_kernel(const float* __restrict__ freqs,
                            const float* __restrict__ rots,
                            const float* __restrict__ coeffs) {
    int w = threadIdx.x;
    if (w < N_WAVES) {
        float f  = freqs[w];
        float r  = rots[w];
        float c0 = coeffs[2 * w];
        float c1 = coeffs[2 * w + 1];
        float sr, cr;
        sincosf(r, &sr, &cr);
        // c0*sin(p) + c1*cos(p) = A * sin(p + ph), A*cos(ph)=c0, A*sin(ph)=c1
        float A  = sqrtf(c0 * c0 + c1 * c1);
        float ph = atan2f(c1, c0);
        const float inv2pi = 0.15915494309189535f;
        g_wp[w] = make_float4(f * cr, f * sr, ph * inv2pi, A);
    }
}

__global__ void __launch_bounds__(TPB)
wave_kernel(const float2* __restrict__ x, float* __restrict__ out, int n) {
    __shared__ float4 swp[N_WAVES];
    if (threadIdx.x < N_WAVES) swp[threadIdx.x] = g_wp[threadIdx.x];
    __syncthreads();

    int base = blockIdx.x * (TPB * PPT) + threadIdx.x;

    float px[PPT], py[PPT], acc[PPT];
#pragma unroll
    for (int j = 0; j < PPT; j++) {
        int i = base + j * TPB;
        float2 v = (i < n) ? x[i] : make_float2(0.f, 0.f);
        px[j] = v.x;
        py[j] = v.y;
        acc[j] = 0.f;
    }

    const float two_pi = 6.283185307179586f;
#pragma unroll 4
    for (int w = 0; w < N_WAVES; w++) {
        float4 p = swp[w];  // broadcast LDS.128, conflict-free
#pragma unroll
        for (int j = 0; j < PPT; j++) {
            // phase in cycles, including the per-wave phase offset
            float u = fmaf(px[j], p.x, fmaf(py[j], p.y, p.z));
            // exact range reduction to [-0.5, 0.5] cycles
            float d = u - rintf(u);
            // MUFU.SIN on [-pi, pi]: accurate region
            acc[j] = fmaf(p.w, __sinf(two_pi * d), acc[j]);
        }
    }

#pragma unroll
    for (int j = 0; j < PPT; j++) {
        int i = base + j * TPB;
        if (i < n) out[i] = acc[j];
    }
}

extern "C" void kernel_launch(void* const* d_in, const int* in_sizes, int n_in,
                              void* d_out, int out_size) {
    const float* x      = (const float*)d_in[0];  // [N,2]
    const float* freqs  = (const float*)d_in[1];  // [W,1]
    const float* rots   = (const float*)d_in[2];  // [W,1]
    const float* coeffs = (const float*)d_in[3];  // [W,2]
    float* out = (float*)d_out;                   // [N,1]

    int n = in_sizes[0] / 2;

    prep_kernel<<<1, N_WAVES>>>(freqs, rots, coeffs);

    int blocks = (n + TPB * PPT - 1) / (TPB * PPT);
    wave_kernel<<<blocks, TPB>>>((const float2*)x, out, n);
}

// round 2
// speedup vs baseline: 1.3816x; 1.3816x over previous
#include <cuda_runtime.h>
#include <cuda_bf16.h>

#define N_WAVES 128
#define TPB 256
#define PPT 2  // points per thread

__global__ void __launch_bounds__(TPB)
wave_kernel(const float2* __restrict__ x,
            const float* __restrict__ freqs,
            const float* __restrict__ rots,
            const float* __restrict__ coeffs,
            float* __restrict__ out, int n) {
    // Fused per-block wave-parameter prep (redundant per block, but avoids a
    // second graph node + launch gap). Threads 0..127 each prep one wave.
    __shared__ float4 swp[N_WAVES];
    if (threadIdx.x < N_WAVES) {
        int w = threadIdx.x;
        float f  = freqs[w];
        float r  = rots[w];
        float c0 = coeffs[2 * w];
        float c1 = coeffs[2 * w + 1];
        float sr, cr;
        sincosf(r, &sr, &cr);
        // c0*sin(p) + c1*cos(p) = A * sin(p + ph)
        float A  = sqrtf(c0 * c0 + c1 * c1);
        float ph = atan2f(c1, c0);
        const float inv2pi = 0.15915494309189535f;
        swp[w] = make_float4(f * cr, f * sr, ph * inv2pi, A);
    }
    __syncthreads();

    int base = blockIdx.x * (TPB * PPT) + threadIdx.x;

    float px[PPT], py[PPT], acc[PPT];
#pragma unroll
    for (int j = 0; j < PPT; j++) {
        int i = base + j * TPB;
        float2 v = (i < n) ? x[i] : make_float2(0.f, 0.f);
        px[j] = v.x;
        py[j] = v.y;
        acc[j] = 0.f;
    }

    const float two_pi = 6.283185307179586f;
#pragma unroll 8
    for (int w = 0; w < N_WAVES; w++) {
        float4 p = swp[w];  // LDS.128 broadcast, conflict-free
#pragma unroll
        for (int j = 0; j < PPT; j++) {
            // phase in cycles, including per-wave phase offset
            float u = fmaf(px[j], p.x, fmaf(py[j], p.y, p.z));
            // exact range reduction to [-0.5, 0.5] cycles (Sterbenz)
            float d = u - rintf(u);
            // MUFU.SIN on [-pi, pi]: accurate region
            acc[j] = fmaf(p.w, __sinf(two_pi * d), acc[j]);
        }
    }

#pragma unroll
    for (int j = 0; j < PPT; j++) {
        int i = base + j * TPB;
        if (i < n) out[i] = acc[j];
    }
}

extern "C" void kernel_launch(void* const* d_in, const int* in_sizes, int n_in,
                              void* d_out, int out_size) {
    const float* x      = (const float*)d_in[0];  // [N,2]
    const float* freqs  = (const float*)d_in[1];  // [W,1]
    const float* rots   = (const float*)d_in[2];  // [W,1]
    const float* coeffs = (const float*)d_in[3];  // [W,2]
    float* out = (float*)d_out;                   // [N,1]

    int n = in_sizes[0] / 2;

    int blocks = (n + TPB * PPT - 1) / (TPB * PPT);
    wave_kernel<<<blocks, TPB>>>((const float2*)x, freqs, rots, coeffs, out, n);
}

// round 3
// speedup vs baseline: 1.3904x; 1.0063x over previous
#include <cuda_runtime.h>
#include <cuda_bf16.h>

#define N_WAVES 128
#define TPB 128
#define PPT 4  // points per thread = 2 packed pairs

typedef unsigned long long u64;

__device__ __forceinline__ u64 pk(float lo, float hi) {
    u64 r;
    asm("mov.b64 %0, {%1, %2};" : "=l"(r) : "f"(lo), "f"(hi));
    return r;
}
__device__ __forceinline__ void upk(u64 v, float& lo, float& hi) {
    asm("mov.b64 {%0, %1}, %2;" : "=f"(lo), "=f"(hi) : "l"(v));
}
__device__ __forceinline__ u64 fma2(u64 a, u64 b, u64 c) {
    u64 d;
    asm("fma.rn.f32x2 %0, %1, %2, %3;" : "=l"(d) : "l"(a), "l"(b), "l"(c));
    return d;
}
__device__ __forceinline__ u64 mul2(u64 a, u64 b) {
    u64 d;
    asm("mul.rn.f32x2 %0, %1, %2;" : "=l"(d) : "l"(a), "l"(b));
    return d;
}
__device__ __forceinline__ float sinap(float a) {
    float r;
    asm("sin.approx.f32 %0, %1;" : "=f"(r) : "f"(a));
    return r;
}

__global__ void __launch_bounds__(TPB)
wave_kernel(const float4* __restrict__ x4,   // 2 points per float4
            const float* __restrict__ freqs,
            const float* __restrict__ rots,
            const float* __restrict__ coeffs,
            float2* __restrict__ out2, int n) {
    // Duplicated wave params in shared: swp[2w] = {(gx,gx),(gy,gy)},
    // swp[2w+1] = {(ph,ph),(A,A)}. ld.shared.v2.b64 -> aligned reg pairs, no packs.
    __shared__ ulonglong2 swp[2 * N_WAVES];
    if (threadIdx.x < N_WAVES) {
        int w = threadIdx.x;
        float f  = freqs[w];
        float r  = rots[w];
        float c0 = coeffs[2 * w];
        float c1 = coeffs[2 * w + 1];
        float sr, cr;
        sincosf(r, &sr, &cr);
        float A  = sqrtf(c0 * c0 + c1 * c1);
        float ph = atan2f(c1, c0) * 0.15915494309189535f;  // cycles
        float gx = f * cr, gy = f * sr;
        ulonglong2 q0, q1;
        q0.x = pk(gx, gx); q0.y = pk(gy, gy);
        q1.x = pk(ph, ph); q1.y = pk(A, A);
        swp[2 * w]     = q0;
        swp[2 * w + 1] = q1;
    }
    __syncthreads();

    int pairsTotal = n >> 1;
    int pA = blockIdx.x * (TPB * PPT / 2) + threadIdx.x;  // float4 index (pair of points)
    int pB = pA + TPB;

    float4 a = (pA < pairsTotal) ? x4[pA] : make_float4(0.f, 0.f, 0.f, 0.f);
    float4 b = (pB < pairsTotal) ? x4[pB] : make_float4(0.f, 0.f, 0.f, 0.f);
    u64 pxA = pk(a.x, a.z), pyA = pk(a.y, a.w);
    u64 pxB = pk(b.x, b.z), pyB = pk(b.y, b.w);
    u64 accA = pk(0.f, 0.f), accB = pk(0.f, 0.f);

    const u64 NEG1  = pk(-1.f, -1.f);
    const u64 TWOPI = pk(6.283185307179586f, 6.283185307179586f);

#pragma unroll 2
    for (int w = 0; w < N_WAVES; w++) {
        ulonglong2 q0 = swp[2 * w];      // (gx,gx),(gy,gy)
        ulonglong2 q1 = swp[2 * w + 1];  // (ph,ph),(A,A)

        // pair A
        u64 uA = fma2(pxA, q0.x, fma2(pyA, q0.y, q1.x));  // phase in cycles
        float ua0, ua1; upk(uA, ua0, ua1);
        u64 nA = pk(rintf(ua0), rintf(ua1));
        u64 dA = fma2(nA, NEG1, uA);          // exact reduce to [-0.5,0.5]
        u64 rA = mul2(dA, TWOPI);
        float ra0, ra1; upk(rA, ra0, ra1);
        u64 sA = pk(sinap(ra0), sinap(ra1));  // MUFU.SIN, accurate range
        accA = fma2(q1.y, sA, accA);

        // pair B
        u64 uB = fma2(pxB, q0.x, fma2(pyB, q0.y, q1.x));
        float ub0, ub1; upk(uB, ub0, ub1);
        u64 nB = pk(rintf(ub0), rintf(ub1));
        u64 dB = fma2(nB, NEG1, uB);
        u64 rB = mul2(dB, TWOPI);
        float rb0, rb1; upk(rB, rb0, rb1);
        u64 sB = pk(sinap(rb0), sinap(rb1));
        accB = fma2(q1.y, sB, accB);
    }

    float o0, o1;
    if (pA < pairsTotal) { upk(accA, o0, o1); out2[pA] = make_float2(o0, o1); }
    if (pB < pairsTotal) { upk(accB, o0, o1); out2[pB] = make_float2(o0, o1); }

    // Odd-n tail: one scalar point handled by a single thread.
    if ((n & 1) && blockIdx.x == 0 && threadIdx.x == 0) {
        float px = ((const float2*)x4)[n - 1].x;
        float py = ((const float2*)x4)[n - 1].y;
        float acc = 0.f;
        for (int w = 0; w < N_WAVES; w++) {
            float gx, gxd, gy, gyd, ph, phd, A, Ad;
            upk(swp[2 * w].x, gx, gxd);
            upk(swp[2 * w].y, gy, gyd);
            upk(swp[2 * w + 1].x, ph, phd);
            upk(swp[2 * w + 1].y, A, Ad);
            float u = fmaf(px, gx, fmaf(py, gy, ph));
            float d = u - rintf(u);
            acc = fmaf(A, sinap(6.283185307179586f * d), acc);
        }
        ((float*)out2)[n - 1] = acc;
    }
}

extern "C" void kernel_launch(void* const* d_in, const int* in_sizes, int n_in,
                              void* d_out, int out_size) {
    const float* x      = (const float*)d_in[0];  // [N,2]
    const float* freqs  = (const float*)d_in[1];  // [W,1]
    const float* rots   = (const float*)d_in[2];  // [W,1]
    const float* coeffs = (const float*)d_in[3];  // [W,2]
    float* out = (float*)d_out;                   // [N,1]

    int n = in_sizes[0] / 2;

    int blocks = (n + TPB * PPT - 1) / (TPB * PPT);
    wave_kernel<<<blocks, TPB>>>((const float4*)x, freqs, rots, coeffs,
                                 (float2*)out, n);
}

// round 4
// speedup vs baseline: 1.4888x; 1.0708x over previous
#include <cuda_runtime.h>
#include <cuda_bf16.h>

#define N_WAVES 128
#define W_MUFU 74        // waves evaluated via MUFU.SIN; rest via FMA-pipe polynomial
#define TPB 256
#define PPT 4            // points per thread = 2 packed pairs

typedef unsigned long long u64;

__device__ __forceinline__ u64 pk(float lo, float hi) {
    u64 r; asm("mov.b64 %0, {%1, %2};" : "=l"(r) : "f"(lo), "f"(hi)); return r;
}
__device__ __forceinline__ void upk(u64 v, float& lo, float& hi) {
    asm("mov.b64 {%0, %1}, %2;" : "=f"(lo), "=f"(hi) : "l"(v));
}
__device__ __forceinline__ u64 pk32(unsigned lo, unsigned hi) {
    u64 r; asm("mov.b64 %0, {%1, %2};" : "=l"(r) : "r"(lo), "r"(hi)); return r;
}
__device__ __forceinline__ void upk32(u64 v, unsigned& lo, unsigned& hi) {
    asm("mov.b64 {%0, %1}, %2;" : "=r"(lo), "=r"(hi) : "l"(v));
}
__device__ __forceinline__ u64 fma2(u64 a, u64 b, u64 c) {
    u64 d; asm("fma.rn.f32x2 %0, %1, %2, %3;" : "=l"(d) : "l"(a), "l"(b), "l"(c)); return d;
}
__device__ __forceinline__ u64 mul2(u64 a, u64 b) {
    u64 d; asm("mul.rn.f32x2 %0, %1, %2;" : "=l"(d) : "l"(a), "l"(b)); return d;
}
__device__ __forceinline__ u64 add2(u64 a, u64 b) {
    u64 d; asm("add.rn.f32x2 %0, %1, %2;" : "=l"(d) : "l"(a), "l"(b)); return d;
}
__device__ __forceinline__ float sinap(float a) {
    float r; asm("sin.approx.f32 %0, %1;" : "=f"(r) : "f"(a)); return r;
}

// sin(2*pi*d), d in [-0.25, 0.25] — degree-9 odd Taylor in d (abs err < 9e-6)
#define C1F  6.2831853071795865f
#define C3F -41.341702240399755f
#define C5F  81.605249275853324f
#define C7F -76.705859753061383f
#define C9F  42.058693944897698f

__global__ void __launch_bounds__(TPB, 3)
wave_kernel(const float4* __restrict__ x4,   // 2 points per float4
            const float* __restrict__ freqs,
            const float* __restrict__ rots,
            const float* __restrict__ coeffs,
            float2* __restrict__ out2, int n) {
    // swp[2w] = {(gx,gx),(gy,gy)}, swp[2w+1] = {(ph_cyc,ph_cyc),(A,A)}
    __shared__ ulonglong2 swp[2 * N_WAVES];
    if (threadIdx.x < N_WAVES) {
        int w = threadIdx.x;
        float f  = freqs[w];
        float r  = rots[w];
        float c0 = coeffs[2 * w];
        float c1 = coeffs[2 * w + 1];
        float sr, cr;
        sincosf(r, &sr, &cr);
        float A  = sqrtf(c0 * c0 + c1 * c1);
        float ph = atan2f(c1, c0) * 0.15915494309189535f;  // cycles
        float gx = f * cr, gy = f * sr;
        ulonglong2 q0, q1;
        q0.x = pk(gx, gx); q0.y = pk(gy, gy);
        q1.x = pk(ph, ph); q1.y = pk(A, A);
        swp[2 * w]     = q0;
        swp[2 * w + 1] = q1;
    }
    __syncthreads();

    int pairsTotal = n >> 1;
    int pA = blockIdx.x * (TPB * PPT / 2) + threadIdx.x;
    int pB = pA + TPB;

    float4 a = (pA < pairsTotal) ? x4[pA] : make_float4(0.f, 0.f, 0.f, 0.f);
    float4 b = (pB < pairsTotal) ? x4[pB] : make_float4(0.f, 0.f, 0.f, 0.f);
    u64 pxA = pk(a.x, a.z), pyA = pk(a.y, a.w);
    u64 pxB = pk(b.x, b.z), pyB = pk(b.y, b.w);
    u64 accA = pk(0.f, 0.f), accB = pk(0.f, 0.f);

    const u64 MAG   = pk(12582912.f, 12582912.f);    // 1.5 * 2^23
    const u64 NMAG  = pk(-12582912.f, -12582912.f);
    const u64 NEG1  = pk(-1.f, -1.f);
    const u64 TWO   = pk(2.f, 2.f);
    const u64 NEGH  = pk(-0.5f, -0.5f);
    const u64 TWOPI = pk(6.283185307179586f, 6.283185307179586f);
    const u64 PC1 = pk(C1F, C1F), PC3 = pk(C3F, C3F), PC5 = pk(C5F, C5F);
    const u64 PC7 = pk(C7F, C7F), PC9 = pk(C9F, C9F);

    // ---- MUFU-path waves ----
#pragma unroll 2
    for (int w = 0; w < W_MUFU; w++) {
        ulonglong2 q0 = swp[2 * w];
        ulonglong2 q1 = swp[2 * w + 1];
        {   // pair A
            u64 u = fma2(pxA, q0.x, fma2(pyA, q0.y, q1.x));  // cycles
            u64 t = add2(u, MAG);
            u64 nn = add2(t, NMAG);           // rint(u), exact
            u64 d = fma2(nn, NEG1, u);        // [-0.5, 0.5]
            u64 r = mul2(d, TWOPI);
            float r0, r1; upk(r, r0, r1);
            u64 s = pk(sinap(r0), sinap(r1));
            accA = fma2(q1.y, s, accA);
        }
        {   // pair B
            u64 u = fma2(pxB, q0.x, fma2(pyB, q0.y, q1.x));
            u64 t = add2(u, MAG);
            u64 nn = add2(t, NMAG);
            u64 d = fma2(nn, NEG1, u);
            u64 r = mul2(d, TWOPI);
            float r0, r1; upk(r, r0, r1);
            u64 s = pk(sinap(r0), sinap(r1));
            accB = fma2(q1.y, s, accB);
        }
    }

    // ---- polynomial-path waves (FMA pipe) ----
#pragma unroll 2
    for (int w = W_MUFU; w < N_WAVES; w++) {
        ulonglong2 q0 = swp[2 * w];
        ulonglong2 q1 = swp[2 * w + 1];
        {   // pair A
            u64 u = fma2(pxA, q0.x, fma2(pyA, q0.y, q1.x));
            u64 t2 = fma2(u, TWO, MAG);       // carries parity of rint(2u) in mantissa bit 0
            u64 n2 = add2(t2, NMAG);          // rint(2u)
            u64 d2 = fma2(n2, NEGH, u);       // [-0.25, 0.25]
            u64 s  = mul2(d2, d2);
            u64 p  = fma2(PC9, s, PC7);
            p = fma2(p, s, PC5);
            p = fma2(p, s, PC3);
            p = fma2(p, s, PC1);
            u64 r = mul2(p, d2);              // sin(2pi*d2)
            unsigned tl, th, rl, rh;
            upk32(t2, tl, th); upk32(r, rl, rh);
            rl ^= (tl << 31); rh ^= (th << 31);   // * (-1)^n2
            accA = fma2(q1.y, pk32(rl, rh), accA);
        }
        {   // pair B
            u64 u = fma2(pxB, q0.x, fma2(pyB, q0.y, q1.x));
            u64 t2 = fma2(u, TWO, MAG);
            u64 n2 = add2(t2, NMAG);
            u64 d2 = fma2(n2, NEGH, u);
            u64 s  = mul2(d2, d2);
            u64 p  = fma2(PC9, s, PC7);
            p = fma2(p, s, PC5);
            p = fma2(p, s, PC3);
            p = fma2(p, s, PC1);
            u64 r = mul2(p, d2);
            unsigned tl, th, rl, rh;
            upk32(t2, tl, th); upk32(r, rl, rh);
            rl ^= (tl << 31); rh ^= (th << 31);
            accB = fma2(q1.y, pk32(rl, rh), accB);
        }
    }

    float o0, o1;
    if (pA < pairsTotal) { upk(accA, o0, o1); out2[pA] = make_float2(o0, o1); }
    if (pB < pairsTotal) { upk(accB, o0, o1); out2[pB] = make_float2(o0, o1); }

    // Odd-n tail: one scalar point via the MUFU path.
    if ((n & 1) && blockIdx.x == 0 && threadIdx.x == 0) {
        float px = ((const float2*)x4)[n - 1].x;
        float py = ((const float2*)x4)[n - 1].y;
        float acc = 0.f;
        for (int w = 0; w < N_WAVES; w++) {
            float gx, gxd, gy, gyd, ph, phd, A, Ad;
            upk(swp[2 * w].x, gx, gxd);
            upk(swp[2 * w].y, gy, gyd);
            upk(swp[2 * w + 1].x, ph, phd);
            upk(swp[2 * w + 1].y, A, Ad);
            float u = fmaf(px, gx, fmaf(py, gy, ph));
            float d = u - rintf(u);
            acc = fmaf(A, sinap(6.283185307179586f * d), acc);
        }
        ((float*)out2)[n - 1] = acc;
    }
}

extern "C" void kernel_launch(void* const* d_in, const int* in_sizes, int n_in,
                              void* d_out, int out_size) {
    const float* x      = (const float*)d_in[0];  // [N,2]
    const float* freqs  = (const float*)d_in[1];  // [W,1]
    const float* rots   = (const float*)d_in[2];  // [W,1]
    const float* coeffs = (const float*)d_in[3];  // [W,2]
    float* out = (float*)d_out;                   // [N,1]

    int n = in_sizes[0] / 2;

    int blocks = (n + TPB * PPT - 1) / (TPB * PPT);
    wave_kernel<<<blocks, TPB>>>((const float4*)x, freqs, rots, coeffs,
                                 (float2*)out, n);
}

// round 5
// speedup vs baseline: 1.6831x; 1.1305x over previous
#include <cuda_runtime.h>
#include <cuda_bf16.h>

#define N_WAVES 128
#define W_MUFU 70        // waves via MUFU.SIN; remaining 58 via FMA-pipe minimax poly
#define TPB 256
#define PPT 2            // points per thread = 1 packed pair

typedef unsigned long long u64;

__device__ __forceinline__ u64 pk(float lo, float hi) {
    u64 r; asm("mov.b64 %0, {%1, %2};" : "=l"(r) : "f"(lo), "f"(hi)); return r;
}
__device__ __forceinline__ void upk(u64 v, float& lo, float& hi) {
    asm("mov.b64 {%0, %1}, %2;" : "=f"(lo), "=f"(hi) : "l"(v));
}
__device__ __forceinline__ u64 pk32(unsigned lo, unsigned hi) {
    u64 r; asm("mov.b64 %0, {%1, %2};" : "=l"(r) : "r"(lo), "r"(hi)); return r;
}
__device__ __forceinline__ void upk32(u64 v, unsigned& lo, unsigned& hi) {
    asm("mov.b64 {%0, %1}, %2;" : "=r"(lo), "=r"(hi) : "l"(v));
}
__device__ __forceinline__ u64 fma2(u64 a, u64 b, u64 c) {
    u64 d; asm("fma.rn.f32x2 %0, %1, %2, %3;" : "=l"(d) : "l"(a), "l"(b), "l"(c)); return d;
}
__device__ __forceinline__ u64 mul2(u64 a, u64 b) {
    u64 d; asm("mul.rn.f32x2 %0, %1, %2;" : "=l"(d) : "l"(a), "l"(b)); return d;
}
__device__ __forceinline__ u64 add2(u64 a, u64 b) {
    u64 d; asm("add.rn.f32x2 %0, %1, %2;" : "=l"(d) : "l"(a), "l"(b)); return d;
}
__device__ __forceinline__ u64 sub2(u64 a, u64 b) {
    u64 d; asm("sub.rn.f32x2 %0, %1, %2;" : "=l"(d) : "l"(a), "l"(b)); return d;
}
__device__ __forceinline__ float sinap(float a) {
    float r; asm("sin.approx.f32 %0, %1;" : "=f"(r) : "f"(a)); return r;
}

// sin(pi*d), d in [-0.5, 0.5]: degree-7 odd minimax, coeffs folded to d-domain
// (x = pi*d, sin(x) ~ x(a1 + a3 x^2 + a5 x^4 + a7 x^6), max abs err ~7e-7)
#define A1F  3.14158197f
#define A3F -5.16714000f
#define A5F  2.54189000f
#define A7F -0.55461700f

__global__ void __launch_bounds__(TPB, 5)
wave_kernel(const float4* __restrict__ x4,   // 2 points per float4
            const float* __restrict__ freqs,
            const float* __restrict__ rots,
            const float* __restrict__ coeffs,
            float2* __restrict__ out2, int n) {
    // MUFU waves (w < W_MUFU): params in cycles.
    // Poly waves: params PRE-DOUBLED (half-cycle domain v = 2u).
    // swp[2w] = {(gx,gx),(gy,gy)}, swp[2w+1] = {(ph,ph),(A,A)}
    __shared__ ulonglong2 swp[2 * N_WAVES];
    if (threadIdx.x < N_WAVES) {
        int w = threadIdx.x;
        float f  = freqs[w];
        float r  = rots[w];
        float c0 = coeffs[2 * w];
        float c1 = coeffs[2 * w + 1];
        float sr, cr;
        sincosf(r, &sr, &cr);
        float A  = sqrtf(c0 * c0 + c1 * c1);
        float ph = atan2f(c1, c0) * 0.15915494309189535f;  // cycles
        float gx = f * cr, gy = f * sr;
        if (w >= W_MUFU) { gx *= 2.f; gy *= 2.f; ph *= 2.f; }  // half-cycle domain
        ulonglong2 q0, q1;
        q0.x = pk(gx, gx); q0.y = pk(gy, gy);
        q1.x = pk(ph, ph); q1.y = pk(A, A);
        swp[2 * w]     = q0;
        swp[2 * w + 1] = q1;
    }
    __syncthreads();

    int pairsTotal = n >> 1;
    int p = blockIdx.x * TPB + threadIdx.x;   // one float4 (pair of points) per thread

    float4 a = (p < pairsTotal) ? x4[p] : make_float4(0.f, 0.f, 0.f, 0.f);
    u64 px = pk(a.x, a.z), py = pk(a.y, a.w);
    u64 acc = pk(0.f, 0.f);

    const u64 MAG   = pk(12582912.f, 12582912.f);    // 1.5 * 2^23
    const u64 TWOPI = pk(6.283185307179586f, 6.283185307179586f);
    const u64 PA1 = pk(A1F, A1F), PA3 = pk(A3F, A3F);
    const u64 PA5 = pk(A5F, A5F), PA7 = pk(A7F, A7F);

    // ---- MUFU-path waves (cycle domain, exact range reduce, MUFU.SIN) ----
#pragma unroll 5
    for (int w = 0; w < W_MUFU; w++) {
        ulonglong2 q0 = swp[2 * w];
        ulonglong2 q1 = swp[2 * w + 1];
        u64 u = fma2(px, q0.x, fma2(py, q0.y, q1.x));  // cycles
        u64 t = add2(u, MAG);
        u64 nn = sub2(t, MAG);            // rint(u), exact
        u64 d = sub2(u, nn);              // [-0.5, 0.5] (Sterbenz, exact)
        u64 r = mul2(d, TWOPI);
        float r0, r1; upk(r, r0, r1);
        u64 s = pk(sinap(r0), sinap(r1));
        acc = fma2(q1.y, s, acc);
    }

    // ---- polynomial-path waves (half-cycle domain, FMA pipe) ----
#pragma unroll 4
    for (int w = W_MUFU; w < N_WAVES; w++) {
        ulonglong2 q0 = swp[2 * w];
        ulonglong2 q1 = swp[2 * w + 1];
        u64 v = fma2(px, q0.x, fma2(py, q0.y, q1.x));  // half-cycles (2u)
        u64 t = add2(v, MAG);             // mantissa bit0 = parity of rint(v)
        u64 nn = sub2(t, MAG);            // rint(v)
        u64 d = sub2(v, nn);              // [-0.5, 0.5]
        u64 s = mul2(d, d);
        u64 pl = fma2(PA7, s, PA5);
        pl = fma2(pl, s, PA3);
        pl = fma2(pl, s, PA1);
        u64 r = mul2(pl, d);              // sin(pi*d)
        unsigned tl, th, rl, rh;
        upk32(t, tl, th); upk32(r, rl, rh);
        rl ^= (tl << 31); rh ^= (th << 31);   // * (-1)^rint(v)  (ALU pipe)
        acc = fma2(q1.y, pk32(rl, rh), acc);
    }

    if (p < pairsTotal) {
        float o0, o1; upk(acc, o0, o1);
        out2[p] = make_float2(o0, o1);
    }

    // Odd-n tail: single scalar point via cycle-domain MUFU path.
    if ((n & 1) && blockIdx.x == 0 && threadIdx.x == 0) {
        float tx = ((const float2*)x4)[n - 1].x;
        float ty = ((const float2*)x4)[n - 1].y;
        float ac = 0.f;
        for (int w = 0; w < N_WAVES; w++) {
            float gx, gxd, gy, gyd, ph, phd, A, Ad;
            upk(swp[2 * w].x, gx, gxd);
            upk(swp[2 * w].y, gy, gyd);
            upk(swp[2 * w + 1].x, ph, phd);
            upk(swp[2 * w + 1].y, A, Ad);
            float sc = (w >= W_MUFU) ? 0.5f : 1.0f;    // undo pre-doubling
            float u = fmaf(tx, gx * sc, fmaf(ty, gy * sc, ph * sc));
            float d = u - rintf(u);
            ac = fmaf(A, sinap(6.283185307179586f * d), ac);
        }
        ((float*)out2)[n - 1] = ac;
    }
}

extern "C" void kernel_launch(void* const* d_in, const int* in_sizes, int n_in,
                              void* d_out, int out_size) {
    const float* x      = (const float*)d_in[0];  // [N,2]
    const float* freqs  = (const float*)d_in[1];  // [W,1]
    const float* rots   = (const float*)d_in[2];  // [W,1]
    const float* coeffs = (const float*)d_in[3];  // [W,2]
    float* out = (float*)d_out;                   // [N,1]

    int n = in_sizes[0] / 2;

    int pairs = (n + 1) / 2;
    int blocks = (pairs + TPB - 1) / TPB;
    wave_kernel<<<blocks, TPB>>>((const float4*)x, freqs, rots, coeffs,
                                 (float2*)out, n);
}

// round 6
// speedup vs baseline: 1.6943x; 1.0066x over previous
#include <cuda_runtime.h>
#include <cuda_bf16.h>

#define N_WAVES 128
#define W_MUFU 70        // waves via MUFU.SIN; remaining 58 via FMA-pipe minimax poly
#define TPB 128
#define PPT 2            // points per thread = 1 packed pair

typedef unsigned long long u64;

__device__ __forceinline__ u64 pk(float lo, float hi) {
    u64 r; asm("mov.b64 %0, {%1, %2};" : "=l"(r) : "f"(lo), "f"(hi)); return r;
}
__device__ __forceinline__ void upk(u64 v, float& lo, float& hi) {
    asm("mov.b64 {%0, %1}, %2;" : "=f"(lo), "=f"(hi) : "l"(v));
}
__device__ __forceinline__ u64 pk32(unsigned lo, unsigned hi) {
    u64 r; asm("mov.b64 %0, {%1, %2};" : "=l"(r) : "r"(lo), "r"(hi)); return r;
}
__device__ __forceinline__ void upk32(u64 v, unsigned& lo, unsigned& hi) {
    asm("mov.b64 {%0, %1}, %2;" : "=r"(lo), "=r"(hi) : "l"(v));
}
__device__ __forceinline__ u64 fma2(u64 a, u64 b, u64 c) {
    u64 d; asm("fma.rn.f32x2 %0, %1, %2, %3;" : "=l"(d) : "l"(a), "l"(b), "l"(c)); return d;
}
__device__ __forceinline__ u64 mul2(u64 a, u64 b) {
    u64 d; asm("mul.rn.f32x2 %0, %1, %2;" : "=l"(d) : "l"(a), "l"(b)); return d;
}
__device__ __forceinline__ u64 add2(u64 a, u64 b) {
    u64 d; asm("add.rn.f32x2 %0, %1, %2;" : "=l"(d) : "l"(a), "l"(b)); return d;
}
__device__ __forceinline__ u64 sub2(u64 a, u64 b) {
    u64 d; asm("sub.rn.f32x2 %0, %1, %2;" : "=l"(d) : "l"(a), "l"(b)); return d;
}
__device__ __forceinline__ float sinap(float a) {
    float r; asm("sin.approx.f32 %0, %1;" : "=f"(r) : "f"(a)); return r;
}

// sin(pi*d), d in [-0.5, 0.5]: degree-7 odd minimax, coeffs folded to d-domain
#define A1F  3.14158197f
#define A3F -5.16714000f
#define A5F  2.54189000f
#define A7F -0.55461700f

__global__ void __launch_bounds__(TPB, 11)
wave_kernel(const float4* __restrict__ x4,   // 2 points per float4
            const float* __restrict__ freqs,
            const float* __restrict__ rots,
            const float* __restrict__ coeffs,
            float2* __restrict__ out2, int n) {
    // MUFU waves (w < W_MUFU): params in cycles.
    // Poly waves: params PRE-DOUBLED (half-cycle domain v = 2u).
    // swp[2w] = {(gx,gx),(gy,gy)}, swp[2w+1] = {(ph,ph),(A,A)}
    __shared__ ulonglong2 swp[2 * N_WAVES];
    if (threadIdx.x < N_WAVES) {
        int w = threadIdx.x;
        float f  = freqs[w];
        float r  = rots[w];
        float c0 = coeffs[2 * w];
        float c1 = coeffs[2 * w + 1];
        float sr, cr;
        sincosf(r, &sr, &cr);
        float A  = sqrtf(c0 * c0 + c1 * c1);
        float ph = atan2f(c1, c0) * 0.15915494309189535f;  // cycles
        float gx = f * cr, gy = f * sr;
        if (w >= W_MUFU) { gx *= 2.f; gy *= 2.f; ph *= 2.f; }  // half-cycle domain
        ulonglong2 q0, q1;
        q0.x = pk(gx, gx); q0.y = pk(gy, gy);
        q1.x = pk(ph, ph); q1.y = pk(A, A);
        swp[2 * w]     = q0;
        swp[2 * w + 1] = q1;
    }
    __syncthreads();

    int pairsTotal = n >> 1;
    int p = blockIdx.x * TPB + threadIdx.x;   // one float4 (pair of points) per thread

    float4 a = (p < pairsTotal) ? x4[p] : make_float4(0.f, 0.f, 0.f, 0.f);
    u64 px = pk(a.x, a.z), py = pk(a.y, a.w);
    u64 acc = pk(0.f, 0.f);

    const u64 MAG   = pk(12582912.f, 12582912.f);    // 1.5 * 2^23
    const u64 TWOPI = pk(6.283185307179586f, 6.283185307179586f);
    const u64 PA1 = pk(A1F, A1F), PA3 = pk(A3F, A3F);
    const u64 PA5 = pk(A5F, A5F), PA7 = pk(A7F, A7F);

    // ---- MUFU-path waves (cycle domain, exact range reduce, MUFU.SIN) ----
#pragma unroll 5
    for (int w = 0; w < W_MUFU; w++) {
        ulonglong2 q0 = swp[2 * w];
        ulonglong2 q1 = swp[2 * w + 1];
        u64 u = fma2(px, q0.x, fma2(py, q0.y, q1.x));  // cycles
        u64 t = add2(u, MAG);
        u64 nn = sub2(t, MAG);            // rint(u), exact
        u64 d = sub2(u, nn);              // [-0.5, 0.5] (Sterbenz, exact)
        u64 r = mul2(d, TWOPI);
        float r0, r1; upk(r, r0, r1);
        u64 s = pk(sinap(r0), sinap(r1));
        acc = fma2(q1.y, s, acc);
    }

    // ---- polynomial-path waves (half-cycle domain, FMA pipe) ----
#pragma unroll 4
    for (int w = W_MUFU; w < N_WAVES; w++) {
        ulonglong2 q0 = swp[2 * w];
        ulonglong2 q1 = swp[2 * w + 1];
        u64 v = fma2(px, q0.x, fma2(py, q0.y, q1.x));  // half-cycles (2u)
        u64 t = add2(v, MAG);             // mantissa bit0 = parity of rint(v)
        u64 nn = sub2(t, MAG);            // rint(v)
        u64 d = sub2(v, nn);              // [-0.5, 0.5]
        u64 s = mul2(d, d);
        u64 pl = fma2(PA7, s, PA5);
        pl = fma2(pl, s, PA3);
        pl = fma2(pl, s, PA1);
        u64 r = mul2(pl, d);              // sin(pi*d)
        unsigned tl, th, rl, rh;
        upk32(t, tl, th); upk32(r, rl, rh);
        rl ^= (tl << 31); rh ^= (th << 31);   // * (-1)^rint(v)  (ALU pipe)
        acc = fma2(q1.y, pk32(rl, rh), acc);
    }

    if (p < pairsTotal) {
        float o0, o1; upk(acc, o0, o1);
        out2[p] = make_float2(o0, o1);
    }

    // Odd-n tail: single scalar point via cycle-domain MUFU path.
    if ((n & 1) && blockIdx.x == 0 && threadIdx.x == 0) {
        float tx = ((const float2*)x4)[n - 1].x;
        float ty = ((const float2*)x4)[n - 1].y;
        float ac = 0.f;
        for (int w = 0; w < N_WAVES; w++) {
            float gx, gxd, gy, gyd, ph, phd, A, Ad;
            upk(swp[2 * w].x, gx, gxd);
            upk(swp[2 * w].y, gy, gyd);
            upk(swp[2 * w + 1].x, ph, phd);
            upk(swp[2 * w + 1].y, A, Ad);
            float sc = (w >= W_MUFU) ? 0.5f : 1.0f;    // undo pre-doubling
            float u = fmaf(tx, gx * sc, fmaf(ty, gy * sc, ph * sc));
            float d = u - rintf(u);
            ac = fmaf(A, sinap(6.283185307179586f * d), ac);
        }
        ((float*)out2)[n - 1] = ac;
    }
}

extern "C" void kernel_launch(void* const* d_in, const int* in_sizes, int n_in,
                              void* d_out, int out_size) {
    const float* x      = (const float*)d_in[0];  // [N,2]
    const float* freqs  = (const float*)d_in[1];  // [W,1]
    const float* rots   = (const float*)d_in[2];  // [W,1]
    const float* coeffs = (const float*)d_in[3];  // [W,2]
    float* out = (float*)d_out;                   // [N,1]

    int n = in_sizes[0] / 2;

    int pairs = (n + 1) / 2;
    int blocks = (pairs + TPB - 1) / TPB;
    wave_kernel<<<blocks, TPB>>>((const float4*)x, freqs, rots, coeffs,
                                 (float2*)out, n);
}